// round 9
// baseline (speedup 1.0000x reference)
#include <cuda_runtime.h>

// EnhancedLesionPenaltyLoss: pred (16,1,128,128,128) fp32 -> scalar loss.
// Grid: 16 batches x 16 row-strips(8 rows) x 3 z-segments (43/43/42)
//     = 768 blocks x 256 threads, __launch_bounds__(256,6) (42-reg budget),
//     single wave (148*6=888 >= 768).
// Software-pipelined z loop: next iteration's v/h loads issue BEFORE the
// current body -> structural load->use distance of one full body (~60 instrs)
// regardless of ptxas scheduling. Accumulators split 2-way to halve the
// serial FADD/FFMA dependency chains.
// Integer threshold compares (inputs non-negative). Exact integer counters.
// Last block (atomic ticket) does the deterministic final reduction.

namespace {
constexpr int NB      = 16;
constexpr int STRIPS  = 16;
constexpr int ZSEGS   = 3;
constexpr int NBLK    = NB * STRIPS * ZSEGS;   // 768
constexpr int THREADS = 256;
constexpr int PLANE4  = 4096;                  // float4 per z-plane
constexpr int NACC    = 6;                     // cmin,cmax,max,sds,s1,s2
constexpr unsigned U01 = 0x3C23D70Au;          // bits of 0.01f
constexpr unsigned U05 = 0x3F000000u;          // bits of 0.5f
}

__device__ float        g_part[NBLK * NACC];
__device__ unsigned int g_ticket = 0;

struct Acc {
    float s1a, s1b, s2a, s2b;
    float mxa, mxb, sds;
    int   cia, cib, cha, chb;
};

__device__ __forceinline__ void body(const float4 v, const float4 h,
                                     const bool do_h, const bool do_w,
                                     float4& prev, Acc& a) {
    // w-direction: intra-vector diffs + cross-vector via shuffle.
    const float nx = __shfl_down_sync(0xffffffffu, v.x, 1);
    float g = fabsf(v.y - v.x) + fabsf(v.z - v.y) + fabsf(v.w - v.z);
    if (do_w) g += fabsf(nx - v.w);

    // h-direction: row+1 (sibling warp's v -> L1 hit).
    if (do_h) {
        g += fabsf(h.x - v.x) + fabsf(h.y - v.y) +
             fabsf(h.z - v.z) + fabsf(h.w - v.w);
    }
    // d-direction: prev slice held in registers.
    g += fabsf(v.x - prev.x) + fabsf(v.y - prev.y) +
         fabsf(v.z - prev.z) + fabsf(v.w - prev.w);
    prev = v;
    a.sds += g;

    // thresholds via integer compares (inputs non-negative), 2-way split.
    const unsigned u0 = __float_as_uint(v.x), u1 = __float_as_uint(v.y);
    const unsigned u2 = __float_as_uint(v.z), u3 = __float_as_uint(v.w);
    if (u0 > U01) { a.cia++; a.s1a += v.x; a.s2a = fmaf(v.x, v.x, a.s2a); }
    if (u1 > U01) { a.cib++; a.s1b += v.y; a.s2b = fmaf(v.y, v.y, a.s2b); }
    if (u2 > U01) { a.cia++; a.s1a += v.z; a.s2a = fmaf(v.z, v.z, a.s2a); }
    if (u3 > U01) { a.cib++; a.s1b += v.w; a.s2b = fmaf(v.w, v.w, a.s2b); }
    if (u0 > U05) a.cha++;
    if (u1 > U05) a.chb++;
    if (u2 > U05) a.cha++;
    if (u3 > U05) a.chb++;
    a.mxa = fmaxf(a.mxa, fmaxf(v.x, v.z));
    a.mxb = fmaxf(a.mxb, fmaxf(v.y, v.w));
}

__global__ __launch_bounds__(THREADS, 6)
void lesion_fused(const float* __restrict__ pred, float* __restrict__ out) {
    const int bid   = blockIdx.x;
    const int b     = bid / (STRIPS * ZSEGS);
    const int rem   = bid % (STRIPS * ZSEGS);
    const int strip = rem / ZSEGS;
    const int zseg  = rem % ZSEGS;
    const int tid   = threadIdx.x;
    const int lane  = tid & 31;
    const int wid   = tid >> 5;

    const float4* __restrict__ p =
        reinterpret_cast<const float4*>(pred) + (long long)b * (PLANE4 * 128);
    const int  o    = strip * 256 + tid;   // float4 index within a plane
    const int  grow = o >> 5;              // global row (lane == col4)
    const bool do_h = (grow < 127);
    const bool do_w = (lane != 31);
    const int  z0   = zseg * 43;           // 0, 43, 86
    const int  zlen = (zseg == 2) ? 42 : 43;

    Acc a = {0.f,0.f,0.f,0.f, 0.f,0.f,0.f, 0,0,0,0};

    // Seed prev with plane z0-1 (z0==0: self-diff contributes 0).
    const int zp = (z0 > 0) ? (z0 - 1) : 0;
    float4 prev = p[zp * PLANE4 + o];

    const float4* pv = p + (long long)z0 * PLANE4 + o;
    const float4* ph = pv + 32;

    // ---- software-pipelined z loop ----
    float4 v = pv[0];
    float4 h;
    if (do_h) h = ph[0];

#pragma unroll 2
    for (int i = 0; i < zlen - 1; ++i) {
        // prefetch next plane BEFORE processing current
        const float4 vn = pv[(i + 1) * PLANE4];
        float4 hn;
        if (do_h) hn = ph[(i + 1) * PLANE4];

        body(v, h, do_h, do_w, prev, a);

        v = vn; h = hn;
    }
    body(v, h, do_h, do_w, prev, a);   // last iteration, no prefetch

    // merge split accumulators (fixed order)
    const float s1  = a.s1a + a.s1b;
    const float s2  = a.s2a + a.s2b;
    const float mx  = fmaxf(a.mxa, a.mxb);
    const int   ci  = a.cia + a.cib;
    const int   ch  = a.cha + a.chb;

    // ---- block reduction (8 warps) ----
    float acc[NACC] = {(float)ci, (float)ch, mx, a.sds, s1, s2};
#pragma unroll
    for (int k = 0; k < NACC; ++k) {
#pragma unroll
        for (int off = 16; off; off >>= 1) {
            const float t = __shfl_xor_sync(0xffffffffu, acc[k], off);
            acc[k] = (k == 2) ? fmaxf(acc[k], t) : (acc[k] + t);
        }
    }
    __shared__ float red[8][NACC];
    __shared__ float fin[NB][NACC];
    __shared__ float lsh[NB];
    __shared__ unsigned int tick_sh;
    if (lane == 0) {
#pragma unroll
        for (int k = 0; k < NACC; ++k) red[wid][k] = acc[k];
    }
    __syncthreads();

    if (tid == 0) {
#pragma unroll
        for (int k = 0; k < NACC; ++k) {
            float r = red[0][k];
#pragma unroll
            for (int w = 1; w < 8; ++w)
                r = (k == 2) ? fmaxf(r, red[w][k]) : (r + red[w][k]);
            g_part[bid * NACC + k] = r;
        }
        __threadfence();
        tick_sh = atomicAdd(&g_ticket, 1u);
    }
    __syncthreads();
    if (tick_sh != (unsigned)(NBLK - 1)) return;

    // ---- last block: deterministic fixed-order final reduction ----
    __threadfence();  // acquire other blocks' g_part writes

    constexpr int PER_B = STRIPS * ZSEGS;  // 48 partials per batch
    if (tid < NB * NACC) {
        const int fb = tid / NACC;
        const int fk = tid % NACC;
        const float* base = &g_part[(fb * PER_B) * NACC + fk];
        float r = base[0];
#pragma unroll
        for (int c = 1; c < PER_B; ++c) {
            const float t = base[c * NACC];
            r = (fk == 2) ? fmaxf(r, t) : (r + t);
        }
        fin[fb][fk] = r;
    }
    __syncthreads();

    if (tid < NB) {
        const float cnt   = fin[tid][0];
        const float chigh = fin[tid][1];
        const float mxv   = fin[tid][2];
        const float sg    = fin[tid][3];
        const float S1    = fin[tid][4];
        const float S2    = fin[tid][5];

        const float invN   = 1.f / 2097152.f;        // 1/128^3
        const float invND3 = 1.f / 6242304.f;        // 1/(3*127*128*128)

        const float act = cnt * invN;
        float loss = fmaxf(0.005f - act, 0.f) * 15.f;

        const float high = chigh * invN;
        loss += fmaxf(high - 0.03f, 0.f) * 5.f;

        const float avg_grad = sg * invND3;
        if (mxv > 0.3f) loss += fminf(avg_grad, 1.f) * 5.f;

        const float cnt_safe = fmaxf(cnt, 1.f);
        const float m  = S1 / cnt_safe;
        const float sq = fmaxf(S2 - 2.f * m * S1 + m * m * cnt, 0.f);
        const bool gate = (act > 0.001f) && (cnt > 1.f);
        const float var = gate ? (sq / fmaxf(cnt - 1.f, 1.f)) : 1.f;
        const float rel_std = sqrtf(var) / (m + 1e-6f);
        const float pen = expf(-5.f * rel_std);
        loss += (gate ? pen : 0.f) * 7.f;

        lsh[tid] = loss;
    }
    __syncthreads();
    if (tid == 0) {
        float t = 0.f;
#pragma unroll
        for (int i = 0; i < NB; ++i) t += lsh[i];
        out[0] = t * (1.f / 16.f);
        g_ticket = 0;  // reset for next (graph-replayed) launch
    }
}

extern "C" void kernel_launch(void* const* d_in, const int* in_sizes, int n_in,
                              void* d_out, int out_size) {
    (void)in_sizes; (void)n_in; (void)out_size;
    const float* pred = (const float*)d_in[0];
    float* out = (float*)d_out;
    lesion_fused<<<NBLK, THREADS>>>(pred, out);
}

// round 10
// speedup vs baseline: 1.0401x; 1.0401x over previous
#include <cuda_runtime.h>

// EnhancedLesionPenaltyLoss: pred (16,1,128,128,128) fp32 -> scalar loss.
// Grid: 16 batches x 16 row-strips(8 rows) x 4 z-segments(32 slices)
//     = 1024 blocks x 256 threads, __launch_bounds__(256,7), single wave.
// cp.async 4-stage smem pipeline: each stage = block's 8-row plane chunk
// (4KB) + 1 halo row (512B). Loads have NO register residency -> structural
// MLP; consumers are LDS.128. h-neighbor comes from the same smem stage
// (no duplicate global read). d-neighbor from prev registers.
// Integer threshold compares (inputs non-negative), exact integer counters.
// Last block (atomic ticket) does the deterministic final reduction.

namespace {
constexpr int NB      = 16;
constexpr int STRIPS  = 16;
constexpr int ZSEGS   = 4;
constexpr int ZLEN    = 32;
constexpr int NBLK    = NB * STRIPS * ZSEGS;   // 1024
constexpr int THREADS = 256;
constexpr int PLANE4  = 4096;                  // float4 per z-plane
constexpr int NACC    = 6;                     // cmin,cmax,max,sds,s1,s2
constexpr int STAGES  = 4;
constexpr int STG_F4  = 288;                   // 8 rows(256) + halo row(32)
constexpr unsigned U01 = 0x3C23D70Au;          // bits of 0.01f
constexpr unsigned U05 = 0x3F000000u;          // bits of 0.5f
}

__device__ float        g_part[NBLK * NACC];
__device__ unsigned int g_ticket = 0;

__device__ __forceinline__ void cp16(unsigned dst, const void* src) {
    asm volatile("cp.async.ca.shared.global [%0], [%1], 16;"
                 :: "r"(dst), "l"(src) : "memory");
}

__global__ __launch_bounds__(THREADS, 7)
void lesion_fused(const float* __restrict__ pred, float* __restrict__ out) {
    const int bid   = blockIdx.x;
    const int zseg  = bid & 3;
    const int strip = (bid >> 2) & 15;
    const int b     = bid >> 6;
    const int tid   = threadIdx.x;
    const int lane  = tid & 31;
    const int wid   = tid >> 5;

    __shared__ float4 sbuf[STAGES * STG_F4];
    __shared__ float  red[8][NACC];
    __shared__ float  fin[NB][NACC];
    __shared__ float  lsh[NB];
    __shared__ unsigned int tick_sh;

    const float4* __restrict__ p =
        reinterpret_cast<const float4*>(pred) + (long long)b * (PLANE4 * 128);
    const int  o    = strip * 256 + tid;   // float4 index within a plane
    const int  grow = o >> 5;              // global row (lane == col4)
    const bool do_h = (grow < 127);
    const bool do_w = (lane != 31);
    const bool halo = (tid < 32) && (strip < 15);
    const int  z0   = zseg * ZLEN;

    // byte pointers for cp.async sources
    const char* gmain = reinterpret_cast<const char*>(p) +
                        (size_t)strip * 4096 + (size_t)tid * 16;
    const char* ghalo = reinterpret_cast<const char*>(p) +
                        (size_t)strip * 4096 + 4096 + (size_t)tid * 16;
    const unsigned sm0 =
        (unsigned)__cvta_generic_to_shared(sbuf) + (unsigned)tid * 16u;

    // Seed prev with plane z0-1 (z0==0: self-diff contributes 0).
    const int zp = (z0 > 0) ? (z0 - 1) : 0;
    float4 prev = p[zp * PLANE4 + o];

    // ---- prologue: issue stages 0..2 ----
#pragma unroll
    for (int k = 0; k < STAGES - 1; ++k) {
        const size_t zoff = (size_t)(z0 + k) * 65536;
        cp16(sm0 + (unsigned)(k * STG_F4 * 16), gmain + zoff);
        if (halo)
            cp16(sm0 + (unsigned)(k * STG_F4 * 16 + 4096), ghalo + zoff);
        asm volatile("cp.async.commit_group;" ::: "memory");
    }

    int   ci = 0, ch = 0;
    float mx = 0.f, sds = 0.f, s1 = 0.f, s2 = 0.f;

    for (int i = 0; i < ZLEN; ++i) {
        asm volatile("cp.async.wait_group 2;" ::: "memory");
        __syncthreads();   // stage i visible to all; stage i-1 reads done

        const int st = i & 3;
        const float4 v = sbuf[st * STG_F4 + tid];
        float4 h;
        if (do_h) h = sbuf[st * STG_F4 + tid + 32];

        // issue stage i+3 (buffer (i+3)%4 == (i-1)%4; barrier above ordered
        // the previous iteration's reads before this write).
        const int zi = i + STAGES - 1;
        if (zi < ZLEN) {
            const size_t zoff = (size_t)(z0 + zi) * 65536;
            const unsigned sdst = sm0 + (unsigned)((zi & 3) * STG_F4 * 16);
            cp16(sdst, gmain + zoff);
            if (halo) cp16(sdst + 4096u, ghalo + zoff);
        }
        asm volatile("cp.async.commit_group;" ::: "memory");

        // ---- math body (R6, proven) ----
        const float nx = __shfl_down_sync(0xffffffffu, v.x, 1);
        float g = fabsf(v.y - v.x) + fabsf(v.z - v.y) + fabsf(v.w - v.z);
        if (do_w) g += fabsf(nx - v.w);
        if (do_h) {
            g += fabsf(h.x - v.x) + fabsf(h.y - v.y) +
                 fabsf(h.z - v.z) + fabsf(h.w - v.w);
        }
        g += fabsf(v.x - prev.x) + fabsf(v.y - prev.y) +
             fabsf(v.z - prev.z) + fabsf(v.w - prev.w);
        prev = v;
        sds += g;

        const float xs[4] = {v.x, v.y, v.z, v.w};
#pragma unroll
        for (int k = 0; k < 4; ++k) {
            const float    x  = xs[k];
            const unsigned xu = __float_as_uint(x);
            if (xu > U01) {                // x > 0.01f
                ci++;
                s1 += x;
                s2  = fmaf(x, x, s2);
            }
            if (xu > U05) ch++;            // x > 0.5f
            mx = fmaxf(mx, x);
        }
    }

    // ---- block reduction (8 warps) ----
    float acc[NACC] = {(float)ci, (float)ch, mx, sds, s1, s2};
#pragma unroll
    for (int k = 0; k < NACC; ++k) {
#pragma unroll
        for (int off = 16; off; off >>= 1) {
            const float t = __shfl_xor_sync(0xffffffffu, acc[k], off);
            acc[k] = (k == 2) ? fmaxf(acc[k], t) : (acc[k] + t);
        }
    }
    if (lane == 0) {
#pragma unroll
        for (int k = 0; k < NACC; ++k) red[wid][k] = acc[k];
    }
    __syncthreads();

    if (tid == 0) {
#pragma unroll
        for (int k = 0; k < NACC; ++k) {
            float r = red[0][k];
#pragma unroll
            for (int w = 1; w < 8; ++w)
                r = (k == 2) ? fmaxf(r, red[w][k]) : (r + red[w][k]);
            g_part[bid * NACC + k] = r;
        }
        __threadfence();
        tick_sh = atomicAdd(&g_ticket, 1u);
    }
    __syncthreads();
    if (tick_sh != (unsigned)(NBLK - 1)) return;

    // ---- last block: deterministic fixed-order final reduction ----
    __threadfence();  // acquire other blocks' g_part writes

    constexpr int PER_B = STRIPS * ZSEGS;  // 64 partials per batch
    if (tid < NB * NACC) {
        const int fb = tid / NACC;
        const int fk = tid % NACC;
        const float* base = &g_part[(fb * PER_B) * NACC + fk];
        float r = base[0];
#pragma unroll
        for (int c = 1; c < PER_B; ++c) {
            const float t = base[c * NACC];
            r = (fk == 2) ? fmaxf(r, t) : (r + t);
        }
        fin[fb][fk] = r;
    }
    __syncthreads();

    if (tid < NB) {
        const float cnt   = fin[tid][0];
        const float chigh = fin[tid][1];
        const float mxv   = fin[tid][2];
        const float sg    = fin[tid][3];
        const float S1    = fin[tid][4];
        const float S2    = fin[tid][5];

        const float invN   = 1.f / 2097152.f;        // 1/128^3
        const float invND3 = 1.f / 6242304.f;        // 1/(3*127*128*128)

        const float act = cnt * invN;
        float loss = fmaxf(0.005f - act, 0.f) * 15.f;

        const float high = chigh * invN;
        loss += fmaxf(high - 0.03f, 0.f) * 5.f;

        const float avg_grad = sg * invND3;
        if (mxv > 0.3f) loss += fminf(avg_grad, 1.f) * 5.f;

        const float cnt_safe = fmaxf(cnt, 1.f);
        const float m  = S1 / cnt_safe;
        const float sq = fmaxf(S2 - 2.f * m * S1 + m * m * cnt, 0.f);
        const bool gate = (act > 0.001f) && (cnt > 1.f);
        const float var = gate ? (sq / fmaxf(cnt - 1.f, 1.f)) : 1.f;
        const float rel_std = sqrtf(var) / (m + 1e-6f);
        const float pen = expf(-5.f * rel_std);
        loss += (gate ? pen : 0.f) * 7.f;

        lsh[tid] = loss;
    }
    __syncthreads();
    if (tid == 0) {
        float t = 0.f;
#pragma unroll
        for (int i = 0; i < NB; ++i) t += lsh[i];
        out[0] = t * (1.f / 16.f);
        g_ticket = 0;  // reset for next (graph-replayed) launch
    }
}

extern "C" void kernel_launch(void* const* d_in, const int* in_sizes, int n_in,
                              void* d_out, int out_size) {
    (void)in_sizes; (void)n_in; (void)out_size;
    const float* pred = (const float*)d_in[0];
    float* out = (float*)d_out;
    lesion_fused<<<NBLK, THREADS>>>(pred, out);
}